// round 13
// baseline (speedup 1.0000x reference)
#include <cuda_runtime.h>
#include <cstdint>

// FOFE encoding (store-drain-floor bound, ~23 us):
//   out[b,s,v] = sum_k alpha^(W-1-k) * [sents[b,s,k] == v],  V=512, W=20
// Warp processes 4 consecutive rows (fewer CTAs/waves, weights hoisted once)
// but chars are loaded ONE ROW AT A TIME (MLP_p1=1) to avoid cross-CTA
// L1tex-queue spread. smem accumulate + 4 x STG.128 evict-first per row.

#define FOFE_V 512
#define FOFE_W 20
#define WARPS_PER_BLOCK 8
#define ROWS_PER_WARP 4

__global__ void __launch_bounds__(WARPS_PER_BLOCK * 32)
fofe_kernel(const int* __restrict__ sents,
            const int* __restrict__ lengths,
            const float* __restrict__ forgetting,
            float* __restrict__ out,
            int n_rows, int tail_n) {
    __shared__ float sh[WARPS_PER_BLOCK][FOFE_V];

    const int warp  = threadIdx.x >> 5;
    const int lane  = threadIdx.x & 31;
    const int wbase = (blockIdx.x * WARPS_PER_BLOCK + warp) * ROWS_PER_WARP;

    // fused lengths tail (block 0, <=256 values)
    if (blockIdx.x == 0 && (int)threadIdx.x < tail_n) {
        out[(size_t)n_rows * FOFE_V + threadIdx.x] = (float)lengths[threadIdx.x];
    }
    if (wbase >= n_rows) return;

    // hoisted per-warp decay weight: w = alpha^(W-1-lane) for lanes 0..19
    const float alpha = __ldg(forgetting);
    float w = 0.0f;
    if (lane < FOFE_W) {
        w = 1.0f;
        const int e = FOFE_W - 1 - lane;
        #pragma unroll
        for (int j = 0; j < FOFE_W - 1; j++) {
            if (j < e) w *= alpha;
        }
    }

    float* s = sh[warp];
    float4* s4 = reinterpret_cast<float4*>(s);
    const float4 z4 = make_float4(0.f, 0.f, 0.f, 0.f);

    #pragma unroll
    for (int j = 0; j < ROWS_PER_WARP; j++) {
        const int row = wbase + j;
        if (row >= n_rows) break;

        // char load for THIS row only (MLP_p1 = 1); overlaps prior store burst
        int c = 0;
        if (lane < FOFE_W) c = __ldg(sents + (size_t)row * FOFE_W + lane);

        // zero 512 floats (4 x STS.128 per lane)
        #pragma unroll
        for (int i = 0; i < 4; i++) s4[lane + i * 32] = z4;
        __syncwarp();

        // scatter-add decay weights
        if (lane < FOFE_W) atomicAdd(&s[c], w);
        __syncwarp();

        // stream out (4 x STG.128 per lane, evict-first)
        float4* orow = reinterpret_cast<float4*>(out + (size_t)row * FOFE_V);
        #pragma unroll
        for (int i = 0; i < 4; i++) {
            const int idx = lane + i * 32;
            __stcs(orow + idx, s4[idx]);
        }
        // next iteration's zeroing is same-lane over the same slots; the two
        // syncwarps above order cross-lane reuse.
    }
}

extern "C" void kernel_launch(void* const* d_in, const int* in_sizes, int n_in,
                              void* d_out, int out_size) {
    const int*   sents      = (const int*)d_in[0];
    const int*   lengths    = (const int*)d_in[1];
    const float* forgetting = (const float*)d_in[2];
    float*       out        = (float*)d_out;

    const int n_rows = in_sizes[0] / FOFE_W;      // B*S
    const int B      = in_sizes[1];

    const long long main_elems = (long long)n_rows * FOFE_V;
    int tail_n = 0;
    if ((long long)out_size > main_elems) {
        long long t = (long long)out_size - main_elems;
        tail_n = (int)(t < B ? t : B);
        if (tail_n > 256) tail_n = 256;
    }

    const int threads = WARPS_PER_BLOCK * 32;
    const int rows_per_block = WARPS_PER_BLOCK * ROWS_PER_WARP;
    const int blocks = (n_rows + rows_per_block - 1) / rows_per_block;
    fofe_kernel<<<blocks, threads>>>(sents, lengths, forgetting, out,
                                     n_rows, tail_n);
}

// round 14
// speedup vs baseline: 1.1015x; 1.1015x over previous
#include <cuda_runtime.h>
#include <cstdint>

// FOFE encoding (FINAL, store-drain-floor bound):
//   out[b,s,v] = sum_k alpha^(W-1-k) * [sents[b,s,k] == v],  V=512, W=20
// 134 MB of mandatory fp32 output through the ~5.9 TB/s SM->L2->DRAM store
// drain sets a ~22.5 us kernel floor (reached; 9 alternative structures all
// matched or regressed). Structure: one warp per row, smem accumulate via
// spread-address atomics, 4 x STG.128 evict-first streaming stores, lengths
// tail fused into block 0. Best measured: 22.91 us kernel / 23.04 us wall.

#define FOFE_V 512
#define FOFE_W 20
#define WARPS_PER_BLOCK 8

__global__ void fofe_fused_kernel(const int* __restrict__ sents,
                                  const int* __restrict__ lengths,
                                  const float* __restrict__ forgetting,
                                  float* __restrict__ out,
                                  int n_rows, int tail_n) {
    __shared__ float sh[WARPS_PER_BLOCK][FOFE_V];

    const int warp = threadIdx.x >> 5;
    const int lane = threadIdx.x & 31;
    const int row  = blockIdx.x * WARPS_PER_BLOCK + warp;

    // fused lengths tail: block 0's first tail_n threads (tail_n <= 256)
    if (blockIdx.x == 0 && (int)threadIdx.x < tail_n) {
        out[(size_t)n_rows * FOFE_V + threadIdx.x] = (float)lengths[threadIdx.x];
    }

    if (row >= n_rows) return;

    float* s = sh[warp];

    // zero the 512-float row buffer (16 floats/lane)
    #pragma unroll
    for (int i = lane; i < FOFE_V; i += 32) s[i] = 0.0f;
    __syncwarp();

    // lanes 0..19: scatter-add decay weight into shared
    if (lane < FOFE_W) {
        const float alpha = forgetting[0];
        const int c = sents[(size_t)row * FOFE_W + lane];
        // w = alpha^(W-1-lane), iterative multiply (<=19 FMULs)
        float w = 1.0f;
        const int e = FOFE_W - 1 - lane;
        #pragma unroll
        for (int j = 0; j < FOFE_W - 1; j++) {
            if (j < e) w *= alpha;
        }
        atomicAdd(&s[c], w);
    }
    __syncwarp();

    // stream out 512 floats as float4 (128 float4, 4 per lane), coalesced,
    // streaming (evict-first) since the output is never re-read.
    float* orow = out + (size_t)row * FOFE_V;
    const float4* sv = reinterpret_cast<const float4*>(s);
    #pragma unroll
    for (int i = 0; i < 4; i++) {
        const int idx = lane + i * 32;
        __stcs(reinterpret_cast<float4*>(orow) + idx, sv[idx]);
    }
}

extern "C" void kernel_launch(void* const* d_in, const int* in_sizes, int n_in,
                              void* d_out, int out_size) {
    const int*   sents      = (const int*)d_in[0];
    const int*   lengths    = (const int*)d_in[1];
    const float* forgetting = (const float*)d_in[2];
    float*       out        = (float*)d_out;

    const int n_rows = in_sizes[0] / FOFE_W;      // B*S
    const int B      = in_sizes[1];

    // tail elements (lengths passthrough) if the harness flattened the tuple
    const long long main_elems = (long long)n_rows * FOFE_V;
    int tail_n = 0;
    if ((long long)out_size > main_elems) {
        long long t = (long long)out_size - main_elems;
        tail_n = (int)(t < B ? t : B);
        if (tail_n > 256) tail_n = 256;  // block 0 handles up to 256
    }

    const int threads = WARPS_PER_BLOCK * 32;
    const int blocks  = (n_rows + WARPS_PER_BLOCK - 1) / WARPS_PER_BLOCK;
    fofe_fused_kernel<<<blocks, threads>>>(sents, lengths, forgetting, out,
                                           n_rows, tail_n);
}